// round 2
// baseline (speedup 1.0000x reference)
#include <cuda_runtime.h>
#include <math.h>
#include <cstdint>

#define B_  64
#define T_  2048
#define I_  128
#define H_  256

#define NG 16      // batch groups (clusters)
#define NS 8       // hidden slices per group (cluster size)
#define NB 4       // batches per group
#define NU 32      // hidden units per slice
#define THREADS 384
#define WSTRIDE 390   // 384 + pad6: stride%32==6 -> conflict-free LDS.64

// ---- SMEM layout (float offsets) ----
#define OFF_W    0
#define SZ_W     (3*32*WSTRIDE)            // 37440
#define OFF_BR   (OFF_W + SZ_W)
#define OFF_BZ   (OFF_BR + 32)
#define OFF_BIN  (OFF_BZ + 32)
#define OFF_BHN  (OFF_BIN + 32)
#define OFF_X    (OFF_BHN + 32)            // 2 x [b][k] : 2*4*128 = 1024
#define OFF_H    (OFF_X + 1024)            // 2 x [b][k] : 2*4*256 = 2048
#define OFF_PX   (OFF_H + 2048)            // [g][q4][b][u] = 3*4*4*32 = 1536
#define OFF_PH   (OFF_PX + 1536)           // 1536
#define OFF_MB   (OFF_PX + 3072)           // 2 mbarriers (16B), 8B aligned
#define SMEM_FLOATS (OFF_MB + 4)
#define SMEM_BYTES  (SMEM_FLOATS * 4)      // ~174.9 KB

// ---- PTX helpers ----
__device__ __forceinline__ uint32_t smem_u32(const void* p) {
    uint32_t a;
    asm("{ .reg .u64 t; cvta.to.shared.u64 t, %1; cvt.u32.u64 %0, t; }" : "=r"(a) : "l"(p));
    return a;
}
#define FFMA2(d, a, b) \
    asm volatile("fma.rn.f32x2 %0, %1, %2, %0;" : "+l"(d) : "l"(a), "l"(b))

__device__ __forceinline__ float psum(unsigned long long v) {
    unsigned lo, hi;
    asm("mov.b64 {%0,%1}, %2;" : "=r"(lo), "=r"(hi) : "l"(v));
    return __uint_as_float(lo) + __uint_as_float(hi);
}

#define MBARRIER_INIT(addr, cnt) \
    asm volatile("mbarrier.init.shared.b64 [%0], %1;" :: "r"(addr), "r"(cnt) : "memory")

#define MBARRIER_EXPECT_TX(addr, bytes) \
    asm volatile("mbarrier.arrive.expect_tx.shared.b64 _, [%0], %1;" :: "r"(addr), "r"(bytes) : "memory")

#define MBARRIER_WAIT_PARITY(mbar, parity) do {                                          \
    uint32_t _m = (mbar); uint32_t _p = (parity); uint32_t _done;                        \
    asm volatile("{\n\t.reg .pred p;\n\t"                                                \
        "mbarrier.try_wait.parity.acquire.cta.shared::cta.b64 p, [%1], %2;\n\t"          \
        "selp.b32 %0, 1, 0, p;\n\t}"                                                     \
        : "=r"(_done) : "r"(_m), "r"(_p) : "memory");                                    \
    if (!_done) {                                                                        \
        asm volatile("{\n\t.reg .pred P1;\n\t"                                           \
            "WAIT_LOOP_%=:\n\t"                                                          \
            "mbarrier.try_wait.parity.acquire.cta.shared::cta.b64 P1, [%0], %1, 0x989680;\n\t" \
            "@P1 bra.uni WAIT_DONE_%=;\n\t"                                              \
            "bra.uni WAIT_LOOP_%=;\n\t"                                                  \
            "WAIT_DONE_%=:\n\t}"                                                         \
            :: "r"(_m), "r"(_p) : "memory");                                             \
    }                                                                                    \
} while (0)

#define ST_ASYNC_F32(raddr, fval, rmbar) \
    asm volatile("st.async.shared::cluster.mbarrier::complete_tx::bytes.u32 [%0], %1, [%2];" \
        :: "r"(raddr), "r"(__float_as_uint(fval)), "r"(rmbar) : "memory")

#define CLUSTER_SYNC() do { \
    asm volatile("barrier.cluster.arrive.aligned;" ::: "memory"); \
    asm volatile("barrier.cluster.wait.aligned;"   ::: "memory"); } while (0)

__global__ void __launch_bounds__(THREADS, 1) __cluster_dims__(NS, 1, 1)
gru_scan_kernel(const float* __restrict__ x,
                const float* __restrict__ Wih,
                const float* __restrict__ Whh,
                const float* __restrict__ bih,
                const float* __restrict__ bhh,
                float* __restrict__ outbuf)
{
    extern __shared__ float smem[];
    const int tid = threadIdx.x;
    const int cta = blockIdx.x;
    const int grp = cta >> 3;
    const int slc = cta & 7;
    const int b0  = grp * NB;
    const int u0  = slc * NU;
    const uint32_t sbase = smem_u32(smem);

    float* hid = outbuf + (size_t)B_ * T_;   // hiddens [B][T][H]

    // ---- one-time: W slice into [g][u][k] rows (stride WSTRIDE), k = [Wih(128) | Whh(256)] ----
    for (int rk = tid; rk < 96 * 384; rk += THREADS) {
        int row = rk / 384;
        int k   = rk - row * 384;
        int g   = row >> 5;
        int u   = row & 31;
        int R   = g * 256 + u0 + u;
        float v = (k < 128) ? Wih[(size_t)R * I_ + k]
                            : Whh[(size_t)R * H_ + (k - 128)];
        smem[OFF_W + (g * 32 + u) * WSTRIDE + k] = v;
    }
    if (tid < 32) {
        int u = tid;
        smem[OFF_BR  + u] = bih[0 * 256 + u0 + u] + bhh[0 * 256 + u0 + u];
        smem[OFF_BZ  + u] = bih[1 * 256 + u0 + u] + bhh[1 * 256 + u0 + u];
        smem[OFF_BIN + u] = bih[2 * 256 + u0 + u];
        smem[OFF_BHN + u] = bhh[2 * 256 + u0 + u];
    }
    // preload x_0 into buffer 0: layout [b][k]
    for (int e = tid; e < 512; e += THREADS) {
        int b = e >> 7, k = e & 127;
        smem[OFF_X + e] = x[((size_t)(b0 + b) * T_ + 0) * I_ + k];
    }
    if (tid == 0) {
        MBARRIER_INIT(sbase + OFF_MB * 4 + 0, 1);
        MBARRIER_INIT(sbase + OFF_MB * 4 + 8, 1);
    }
    __syncthreads();
    CLUSTER_SYNC();    // peers' mbarriers initialized before any st.async

    // peer SMEM bases (used by combine threads)
    uint32_t pb[8];
    #pragma unroll
    for (int r = 0; r < 8; ++r)
        asm("mapa.shared::cluster.u32 %0, %1, %2;" : "=r"(pb[r]) : "r"(sbase), "r"(r));

    const int wid = tid >> 5;
    const int g   = wid >> 2;     // gate 0..2
    const int q4  = wid & 3;      // K quarter 0..3
    const int u   = tid & 31;
    const float* wrow = smem + OFF_W + (g * 32 + u) * WSTRIDE;

    for (int t = 0; t < T_; ++t) {
        const int p = t & 1;
        const int q = p ^ 1;

        if (tid == 0 && t + 1 < T_)
            MBARRIER_EXPECT_TX(sbase + OFF_MB * 4 + q * 8, 4096u);

        // prefetch x_{t+1} via cp.async (fire & forget)
        if (t + 1 < T_ && tid < 128) {
            int b = tid >> 5, c = tid & 31;
            uint32_t dst = sbase + (OFF_X + q * 512 + b * 128 + c * 4) * 4;
            const float* src = x + ((size_t)(b0 + b) * T_ + (t + 1)) * I_ + c * 4;
            asm volatile("cp.async.cg.shared.global [%0], [%1], 16;" :: "r"(dst), "l"(src));
            asm volatile("cp.async.commit_group;" ::: "memory");
        }

        // ---- x-phase: acc over k-pairs (f32x2: lo=even k, hi=odd k) ----
        unsigned long long a0 = 0, a1 = 0, a2 = 0, a3 = 0;
        {
            const float* xq = smem + OFF_X + p * 512;
            const int kx = q4 * 32;
            #pragma unroll
            for (int j = 0; j < 16; ++j) {
                unsigned long long w =
                    *reinterpret_cast<const unsigned long long*>(wrow + kx + 2 * j);
                FFMA2(a0, w, *reinterpret_cast<const unsigned long long*>(xq + 0 * 128 + kx + 2 * j));
                FFMA2(a1, w, *reinterpret_cast<const unsigned long long*>(xq + 1 * 128 + kx + 2 * j));
                FFMA2(a2, w, *reinterpret_cast<const unsigned long long*>(xq + 2 * 128 + kx + 2 * j));
                FFMA2(a3, w, *reinterpret_cast<const unsigned long long*>(xq + 3 * 128 + kx + 2 * j));
            }
        }
        // store x-partials (hidden under the upcoming mbarrier wait)
        {
            float* sp = smem + OFF_PX + ((g * 4 + q4) * 4) * 32 + u;
            sp[0 * 32] = psum(a0); sp[1 * 32] = psum(a1);
            sp[2 * 32] = psum(a2); sp[3 * 32] = psum(a3);
        }

        if (t > 0) {
            const uint32_t parity = ((unsigned)(t - 1) >> 1) & 1u;
            MBARRIER_WAIT_PARITY(sbase + OFF_MB * 4 + p * 8, parity);

            // ---- h-phase ----
            unsigned long long h0 = 0, h1 = 0, h2 = 0, h3 = 0;
            const float* hq = smem + OFF_H + p * 1024;
            const int kh = q4 * 64;
            #pragma unroll
            for (int j = 0; j < 32; ++j) {
                unsigned long long w =
                    *reinterpret_cast<const unsigned long long*>(wrow + 128 + kh + 2 * j);
                FFMA2(h0, w, *reinterpret_cast<const unsigned long long*>(hq + 0 * 256 + kh + 2 * j));
                FFMA2(h1, w, *reinterpret_cast<const unsigned long long*>(hq + 1 * 256 + kh + 2 * j));
                FFMA2(h2, w, *reinterpret_cast<const unsigned long long*>(hq + 2 * 256 + kh + 2 * j));
                FFMA2(h3, w, *reinterpret_cast<const unsigned long long*>(hq + 3 * 256 + kh + 2 * j));
            }
            float* sp = smem + OFF_PH + ((g * 4 + q4) * 4) * 32 + u;
            sp[0 * 32] = psum(h0); sp[1 * 32] = psum(h1);
            sp[2 * 32] = psum(h2); sp[3 * 32] = psum(h3);
        }

        if (t + 1 < T_ && tid < 128)
            asm volatile("cp.async.wait_group 0;" ::: "memory");
        __syncthreads();   // (A) partials + x prefetch visible

        // ---- combine: 128 threads, (uu, bb) ----
        if (tid < 128) {
            const int uu = tid & 31;
            const int bb = tid >> 5;
            float sx0 = 0.f, sx1 = 0.f, sx2 = 0.f;
            float sh0 = 0.f, sh1 = 0.f, sh2 = 0.f;
            #pragma unroll
            for (int qq = 0; qq < 4; ++qq) {
                sx0 += smem[OFF_PX + ((0 * 4 + qq) * 4 + bb) * 32 + uu];
                sx1 += smem[OFF_PX + ((1 * 4 + qq) * 4 + bb) * 32 + uu];
                sx2 += smem[OFF_PX + ((2 * 4 + qq) * 4 + bb) * 32 + uu];
            }
            float hprev = 0.f;
            if (t > 0) {
                #pragma unroll
                for (int qq = 0; qq < 4; ++qq) {
                    sh0 += smem[OFF_PH + ((0 * 4 + qq) * 4 + bb) * 32 + uu];
                    sh1 += smem[OFF_PH + ((1 * 4 + qq) * 4 + bb) * 32 + uu];
                    sh2 += smem[OFF_PH + ((2 * 4 + qq) * 4 + bb) * 32 + uu];
                }
                hprev = smem[OFF_H + p * 1024 + bb * 256 + u0 + uu];
            }
            const float pre_r = sx0 + sh0 + smem[OFF_BR + uu];
            const float pre_z = sx1 + sh1 + smem[OFF_BZ + uu];
            const float r = __fdividef(1.f, 1.f + __expf(-pre_r));
            const float z = __fdividef(1.f, 1.f + __expf(-pre_z));
            const float v = (sx2 + smem[OFF_BIN + uu]) + r * (sh2 + smem[OFF_BHN + uu]);
            const float nn = 1.f - __fdividef(2.f, __expf(2.f * v) + 1.f);   // tanh(v)
            const float hnew = (1.f - z) * nn + z * hprev;

            hid[((size_t)(b0 + bb) * T_ + t) * H_ + u0 + uu] = hnew;

            if (t + 1 < T_) {
                const uint32_t off   = (uint32_t)(OFF_H + q * 1024 + bb * 256 + u0 + uu) * 4;
                const uint32_t mboff = (uint32_t)(OFF_MB * 4 + q * 8);
                #pragma unroll
                for (int r8 = 0; r8 < 8; ++r8)
                    ST_ASYNC_F32(pb[r8] + off, hnew, pb[r8] + mboff);
            }
        }
        __syncthreads();   // (B) combine done; safe to reuse partial buffers / sX next step
    }

    CLUSTER_SYNC();        // no CTA exits while peers could still reference its SMEM
}

// outputs[b,t] = hiddens[b,t,:] . W_o + b_o
__global__ void gru_out_kernel(const float* __restrict__ Wo,
                               const float* __restrict__ bo,
                               float* __restrict__ outbuf)
{
    int gw   = (int)((blockIdx.x * blockDim.x + threadIdx.x) >> 5);
    int lane = threadIdx.x & 31;
    if (gw >= B_ * T_) return;

    const float* hrow = outbuf + (size_t)B_ * T_ + (size_t)gw * H_;
    float s = 0.f;
    #pragma unroll
    for (int c = 0; c < 8; ++c) {
        int k = c * 32 + lane;
        s += hrow[k] * __ldg(&Wo[k]);
    }
    #pragma unroll
    for (int off = 16; off; off >>= 1)
        s += __shfl_xor_sync(0xffffffffu, s, off);
    if (lane == 0) outbuf[gw] = s + __ldg(&bo[0]);
}

extern "C" void kernel_launch(void* const* d_in, const int* in_sizes, int n_in,
                              void* d_out, int out_size)
{
    const float* x   = (const float*)d_in[0];
    const float* Wih = (const float*)d_in[1];
    const float* Whh = (const float*)d_in[2];
    const float* bih = (const float*)d_in[3];
    const float* bhh = (const float*)d_in[4];
    const float* Wo  = (const float*)d_in[5];
    const float* bo  = (const float*)d_in[6];
    float* out = (float*)d_out;

    cudaFuncSetAttribute(gru_scan_kernel,
                         cudaFuncAttributeMaxDynamicSharedMemorySize, SMEM_BYTES);

    gru_scan_kernel<<<NG * NS, THREADS, SMEM_BYTES>>>(x, Wih, Whh, bih, bhh, out);
    gru_out_kernel<<<(B_ * T_ * 32) / 256, 256>>>(Wo, bo, out);
}

// round 3
// speedup vs baseline: 1.5022x; 1.5022x over previous
#include <cuda_runtime.h>
#include <math.h>
#include <cstdint>

#define B_  64
#define T_  2048
#define I_  128
#define H_  256

#define NG 16      // batch groups
#define NS 8       // hidden slices per group
#define NB 4       // batches per group
#define NU 32      // hidden units per slice
#define THREADS 384
#define WSTRIDE 386   // even (8B-aligned rows), s==2 mod 64 -> conflict-free LDS.64 per half-warp

// ---- SMEM layout (float offsets, all even) ----
#define OFF_W    0
#define SZ_W     (3*32*WSTRIDE)            // 37056
#define OFF_BR   (OFF_W + SZ_W)
#define OFF_BZ   (OFF_BR + 32)
#define OFF_BIN  (OFF_BZ + 32)
#define OFF_BHN  (OFF_BIN + 32)
#define OFF_X    (OFF_BHN + 32)            // 2 x [b][128] = 1024
#define OFF_H    (OFF_X + 1024)            // 2 x [b][256] = 2048
#define OFF_PX   (OFF_H + 2048)            // [g][q4][b][u] = 1536
#define OFF_PH   (OFF_PX + 1536)           // 1536
#define SMEM_FLOATS (OFF_PH + 1536)
#define SMEM_BYTES  (SMEM_FLOATS * 4)      // ~173.3 KB

__device__ unsigned g_flags[NG];           // zero-init; reset by out kernel each launch

__device__ __forceinline__ uint32_t smem_u32(const void* p) {
    uint32_t a;
    asm("{ .reg .u64 t; cvta.to.shared.u64 t, %1; cvt.u32.u64 %0, t; }" : "=r"(a) : "l"(p));
    return a;
}
__device__ __forceinline__ unsigned ld_acquire(const unsigned* p) {
    unsigned v;
    asm volatile("ld.global.acquire.gpu.u32 %0, [%1];" : "=r"(v) : "l"(p) : "memory");
    return v;
}
#define FFMA2(d, a, b) \
    asm volatile("fma.rn.f32x2 %0, %1, %2, %0;" : "+l"(d) : "l"(a), "l"(b))

__device__ __forceinline__ float psum(unsigned long long v) {
    unsigned lo, hi;
    asm("mov.b64 {%0,%1}, %2;" : "=r"(lo), "=r"(hi) : "l"(v));
    return __uint_as_float(lo) + __uint_as_float(hi);
}

__global__ void __launch_bounds__(THREADS, 1)
gru_scan_kernel(const float* __restrict__ x,
                const float* __restrict__ Wih,
                const float* __restrict__ Whh,
                const float* __restrict__ bih,
                const float* __restrict__ bhh,
                float* __restrict__ outbuf)
{
    extern __shared__ float smem[];
    const int tid = threadIdx.x;
    const int cta = blockIdx.x;
    const int grp = cta >> 3;
    const int slc = cta & 7;
    const int b0  = grp * NB;
    const int u0  = slc * NU;
    const uint32_t sbase = smem_u32(smem);

    float* hid = outbuf + (size_t)B_ * T_;   // hiddens [B][T][H]

    // ---- one-time: W slice into [g][u][k] rows (row stride WSTRIDE); k = [Wih(128)|Whh(256)] ----
    for (int rk = tid; rk < 96 * 384; rk += THREADS) {
        int row = rk / 384;
        int k   = rk - row * 384;
        int g   = row >> 5;
        int u   = row & 31;
        int R   = g * 256 + u0 + u;
        float v = (k < 128) ? Wih[(size_t)R * I_ + k]
                            : Whh[(size_t)R * H_ + (k - 128)];
        smem[OFF_W + (g * 32 + u) * WSTRIDE + k] = v;
    }
    if (tid < 32) {
        int u = tid;
        smem[OFF_BR  + u] = bih[0 * 256 + u0 + u] + bhh[0 * 256 + u0 + u];
        smem[OFF_BZ  + u] = bih[1 * 256 + u0 + u] + bhh[1 * 256 + u0 + u];
        smem[OFF_BIN + u] = bih[2 * 256 + u0 + u];
        smem[OFF_BHN + u] = bhh[2 * 256 + u0 + u];
    }
    // preload x_0 into buffer 0: layout [b][k]
    for (int e = tid; e < 512; e += THREADS) {
        int b = e >> 7, k = e & 127;
        smem[OFF_X + e] = x[((size_t)(b0 + b) * T_ + 0) * I_ + k];
    }
    __syncthreads();

    const int wid = tid >> 5;
    const int g   = wid >> 2;      // gate 0..2
    const int q4  = wid & 3;       // K quarter 0..3
    const int u   = tid & 31;
    const float* wrow = smem + OFF_W + (g * 32 + u) * WSTRIDE;
    const unsigned* flagp = &g_flags[grp];

    for (int t = 0; t < T_; ++t) {
        const int p = t & 1;
        const int q = p ^ 1;

        // issue x_{t+1} prefetch early (warps 4-7)
        if (t + 1 < T_ && wid >= 4 && wid < 8) {
            int e = tid - 128;           // 0..127
            int b = e >> 5, c = e & 31;
            uint32_t dst = sbase + (OFF_X + q * 512 + b * 128 + c * 4) * 4;
            const float* src = x + ((size_t)(b0 + b) * T_ + (t + 1)) * I_ + c * 4;
            asm volatile("cp.async.cg.shared.global [%0], [%1], 16;" :: "r"(dst), "l"(src));
            asm volatile("cp.async.commit_group;" ::: "memory");
        }

        // ---- x-phase GEMM (independent of h_{t-1}; hides peers' publish latency) ----
        {
            unsigned long long a0 = 0, a1 = 0, a2 = 0, a3 = 0;
            const float* xq = smem + OFF_X + p * 512;
            const int kx = q4 * 32;
            #pragma unroll
            for (int j = 0; j < 16; ++j) {
                unsigned long long w =
                    *reinterpret_cast<const unsigned long long*>(wrow + kx + 2 * j);
                FFMA2(a0, w, *reinterpret_cast<const unsigned long long*>(xq + 0 * 128 + kx + 2 * j));
                FFMA2(a1, w, *reinterpret_cast<const unsigned long long*>(xq + 1 * 128 + kx + 2 * j));
                FFMA2(a2, w, *reinterpret_cast<const unsigned long long*>(xq + 2 * 128 + kx + 2 * j));
                FFMA2(a3, w, *reinterpret_cast<const unsigned long long*>(xq + 3 * 128 + kx + 2 * j));
            }
            float* sp = smem + OFF_PX + ((g * 4 + q4) * 4) * 32 + u;
            sp[0 * 32] = psum(a0); sp[1 * 32] = psum(a1);
            sp[2 * 32] = psum(a2); sp[3 * 32] = psum(a3);
        }

        // ---- poll + load h_{t-1} (warps 8-11 only; one K-quarter each) ----
        if (t > 0 && wid >= 8) {
            const unsigned target = 8u * (unsigned)t;
            while (ld_acquire(flagp) < target) { }
            const int q4l  = wid & 3;
            const int lane = u;
            #pragma unroll
            for (int r = 0; r < 2; ++r) {
                int c  = lane + r * 32;         // chunk 0..63
                int b  = c >> 4;
                int kk = (c & 15) * 4;
                float4 v = *reinterpret_cast<const float4*>(
                    &hid[((size_t)(b0 + b) * T_ + (t - 1)) * H_ + q4l * 64 + kk]);
                *reinterpret_cast<float4*>(&smem[OFF_H + p * 1024 + b * 256 + q4l * 64 + kk]) = v;
            }
        }
        __syncthreads();   // (A) h_{t-1} in sH; px visible

        // ---- h-phase GEMM ----
        if (t > 0) {
            unsigned long long a0 = 0, a1 = 0, a2 = 0, a3 = 0;
            const float* hq = smem + OFF_H + p * 1024;
            const int kh = q4 * 64;
            #pragma unroll
            for (int j = 0; j < 32; ++j) {
                unsigned long long w =
                    *reinterpret_cast<const unsigned long long*>(wrow + 128 + kh + 2 * j);
                FFMA2(a0, w, *reinterpret_cast<const unsigned long long*>(hq + 0 * 256 + kh + 2 * j));
                FFMA2(a1, w, *reinterpret_cast<const unsigned long long*>(hq + 1 * 256 + kh + 2 * j));
                FFMA2(a2, w, *reinterpret_cast<const unsigned long long*>(hq + 2 * 256 + kh + 2 * j));
                FFMA2(a3, w, *reinterpret_cast<const unsigned long long*>(hq + 3 * 256 + kh + 2 * j));
            }
            float* sp = smem + OFF_PH + ((g * 4 + q4) * 4) * 32 + u;
            sp[0 * 32] = psum(a0); sp[1 * 32] = psum(a1);
            sp[2 * 32] = psum(a2); sp[3 * 32] = psum(a3);
        }

        if (t + 1 < T_ && wid >= 4 && wid < 8)
            asm volatile("cp.async.wait_group 0;" ::: "memory");
        __syncthreads();   // (B) ph visible; x_{t+1} landed

        // ---- combine: warps 0-3, thread = (bb, uu) ----
        if (tid < 128) {
            const int uu = tid & 31;
            const int bb = tid >> 5;
            float sx0 = 0.f, sx1 = 0.f, sx2 = 0.f;
            float sh0 = 0.f, sh1 = 0.f, sh2 = 0.f;
            #pragma unroll
            for (int qq = 0; qq < 4; ++qq) {
                sx0 += smem[OFF_PX + ((0 * 4 + qq) * 4 + bb) * 32 + uu];
                sx1 += smem[OFF_PX + ((1 * 4 + qq) * 4 + bb) * 32 + uu];
                sx2 += smem[OFF_PX + ((2 * 4 + qq) * 4 + bb) * 32 + uu];
            }
            float hprev = 0.f;
            if (t > 0) {
                #pragma unroll
                for (int qq = 0; qq < 4; ++qq) {
                    sh0 += smem[OFF_PH + ((0 * 4 + qq) * 4 + bb) * 32 + uu];
                    sh1 += smem[OFF_PH + ((1 * 4 + qq) * 4 + bb) * 32 + uu];
                    sh2 += smem[OFF_PH + ((2 * 4 + qq) * 4 + bb) * 32 + uu];
                }
                hprev = smem[OFF_H + p * 1024 + bb * 256 + u0 + uu];
            }
            const float pre_r = sx0 + sh0 + smem[OFF_BR + uu];
            const float pre_z = sx1 + sh1 + smem[OFF_BZ + uu];
            const float r = __fdividef(1.f, 1.f + __expf(-pre_r));
            const float z = __fdividef(1.f, 1.f + __expf(-pre_z));
            const float v = (sx2 + smem[OFF_BIN + uu]) + r * (sh2 + smem[OFF_BHN + uu]);
            const float nn = 1.f - __fdividef(2.f, __expf(2.f * v) + 1.f);   // tanh(v)
            const float hnew = (1.f - z) * nn + z * hprev;

            hid[((size_t)(b0 + bb) * T_ + t) * H_ + u0 + uu] = hnew;
        }
        __syncthreads();   // (C) hid stores done block-wide
        if (tid == 0) {
            __threadfence();                   // cumulative: publishes combine stores
            atomicAdd((unsigned*)flagp, 1u);
        }
    }
}

// outputs[b,t] = hiddens[b,t,:] . W_o + b_o ; also resets flags for graph replay
__global__ void gru_out_kernel(const float* __restrict__ Wo,
                               const float* __restrict__ bo,
                               float* __restrict__ outbuf)
{
    if (blockIdx.x == 0 && threadIdx.x < NG) g_flags[threadIdx.x] = 0u;

    int gw   = (int)((blockIdx.x * blockDim.x + threadIdx.x) >> 5);
    int lane = threadIdx.x & 31;
    if (gw >= B_ * T_) return;

    const float* hrow = outbuf + (size_t)B_ * T_ + (size_t)gw * H_;
    float s = 0.f;
    #pragma unroll
    for (int c = 0; c < 8; ++c) {
        int k = c * 32 + lane;
        s += hrow[k] * __ldg(&Wo[k]);
    }
    #pragma unroll
    for (int off = 16; off; off >>= 1)
        s += __shfl_xor_sync(0xffffffffu, s, off);
    if (lane == 0) outbuf[gw] = s + __ldg(&bo[0]);
}

extern "C" void kernel_launch(void* const* d_in, const int* in_sizes, int n_in,
                              void* d_out, int out_size)
{
    const float* x   = (const float*)d_in[0];
    const float* Wih = (const float*)d_in[1];
    const float* Whh = (const float*)d_in[2];
    const float* bih = (const float*)d_in[3];
    const float* bhh = (const float*)d_in[4];
    const float* Wo  = (const float*)d_in[5];
    const float* bo  = (const float*)d_in[6];
    float* out = (float*)d_out;

    cudaFuncSetAttribute(gru_scan_kernel,
                         cudaFuncAttributeMaxDynamicSharedMemorySize, SMEM_BYTES);

    gru_scan_kernel<<<NG * NS, THREADS, SMEM_BYTES>>>(x, Wih, Whh, bih, bhh, out);
    gru_out_kernel<<<(B_ * T_ * 32) / 256, 256>>>(Wo, bo, out);
}

// round 4
// speedup vs baseline: 1.5409x; 1.0258x over previous
#include <cuda_runtime.h>
#include <math.h>
#include <cstdint>

#define B_  64
#define T_  2048
#define I_  128
#define H_  256

#define NG 16      // batch groups
#define NS 8       // hidden slices per group
#define NB 4       // batches per group
#define NU 32      // hidden units per slice
#define THREADS 256
#define WSTRIDE 388   // %32==4 -> conflict-free LDS.128 of weight rows; rows 16B-aligned

// ---- SMEM layout (float offsets) ----
#define OFF_W    0
#define SZ_W     (3*32*WSTRIDE)            // 37248
#define OFF_BR   (OFF_W + SZ_W)
#define OFF_BZ   (OFF_BR + 32)
#define OFF_BIN  (OFF_BZ + 32)
#define OFF_BHN  (OFF_BIN + 32)
#define OFF_X    (OFF_BHN + 32)            // 2 x [b][128] = 1024
#define OFF_H    (OFF_X + 1024)            // 2 x [b][256] = 2048
#define OFF_PX   (OFF_H + 2048)            // 2 x [g][b][chunk4][u] = 2*1536
#define OFF_PH   (OFF_PX + 3072)           // [g][b][chunk8][u] = 3072
#define SMEM_FLOATS (OFF_PH + 3072)
#define SMEM_BYTES  (SMEM_FLOATS * 4)      // ~182 KB

typedef unsigned long long ull;

__device__ unsigned g_flags[NG];           // zero-init; reset by out kernel for graph replay

__device__ __forceinline__ uint32_t smem_u32(const void* p) {
    uint32_t a;
    asm("{ .reg .u64 t; cvta.to.shared.u64 t, %1; cvt.u32.u64 %0, t; }" : "=r"(a) : "l"(p));
    return a;
}
__device__ __forceinline__ unsigned ld_acquire(const unsigned* p) {
    unsigned v;
    asm volatile("ld.global.acquire.gpu.u32 %0, [%1];" : "=r"(v) : "l"(p) : "memory");
    return v;
}
__device__ __forceinline__ void red_release_add(unsigned* p, unsigned v) {
    asm volatile("red.release.gpu.global.add.u32 [%0], %1;" :: "l"(p), "r"(v) : "memory");
}
#define FFMA2(d, a, b) \
    asm volatile("fma.rn.f32x2 %0, %1, %2, %0;" : "+l"(d) : "l"(a), "l"(b))

__device__ __forceinline__ float psum(ull v) {
    unsigned lo, hi;
    asm("mov.b64 {%0,%1}, %2;" : "=r"(lo), "=r"(hi) : "l"(v));
    return __uint_as_float(lo) + __uint_as_float(hi);
}

__global__ void __launch_bounds__(THREADS, 1)
gru_scan_kernel(const float* __restrict__ x,
                const float* __restrict__ Wih,
                const float* __restrict__ Whh,
                const float* __restrict__ bih,
                const float* __restrict__ bhh,
                float* __restrict__ outbuf)
{
    extern __shared__ float smem[];
    const int tid = threadIdx.x;
    const int cta = blockIdx.x;
    const int grp = cta >> 3;
    const int slc = cta & 7;
    const int b0  = grp * NB;
    const int u0  = slc * NU;
    const uint32_t sbase = smem_u32(smem);

    float* hid = outbuf + (size_t)B_ * T_;   // hiddens [B][T][H]

    // ---- one-time: W slice into [g][u][k] rows (stride WSTRIDE); k = [Wih(128)|Whh(256)] ----
    for (int rk = tid; rk < 96 * 384; rk += THREADS) {
        int row = rk / 384;
        int k   = rk - row * 384;
        int g   = row >> 5;
        int u   = row & 31;
        int R   = g * 256 + u0 + u;
        float v = (k < 128) ? Wih[(size_t)R * I_ + k]
                            : Whh[(size_t)R * H_ + (k - 128)];
        smem[OFF_W + (g * 32 + u) * WSTRIDE + k] = v;
    }
    if (tid < 32) {
        int u = tid;
        smem[OFF_BR  + u] = bih[0 * 256 + u0 + u] + bhh[0 * 256 + u0 + u];
        smem[OFF_BZ  + u] = bih[1 * 256 + u0 + u] + bhh[1 * 256 + u0 + u];
        smem[OFF_BIN + u] = bih[2 * 256 + u0 + u];
        smem[OFF_BHN + u] = bhh[2 * 256 + u0 + u];
    }
    // preload x_0 into buffer 0: layout [b][k]
    for (int e = tid; e < 512; e += THREADS) {
        int b = e >> 7, k = e & 127;
        smem[OFF_X + e] = x[((size_t)(b0 + b) * T_ + 0) * I_ + k];
    }
    __syncthreads();

    const int wid = tid >> 5;
    const int u   = tid & 31;
    const unsigned* flagp = &g_flags[grp];

    // per-lane weight row bases for the 3 gates
    const float* wr0 = smem + OFF_W + (0 * 32 + u) * WSTRIDE;
    const float* wr1 = smem + OFF_W + (1 * 32 + u) * WSTRIDE;
    const float* wr2 = smem + OFF_W + (2 * 32 + u) * WSTRIDE;

    for (int t = 0; t < T_; ++t) {
        const int p = t & 1;
        const int q = p ^ 1;

        if (wid < 4) {
            // ---- prefetch x_{t+1} (1 float4 per lane) ----
            if (t + 1 < T_) {
                int b = wid, c = u;
                uint32_t dst = sbase + (OFF_X + q * 512 + b * 128 + c * 4) * 4;
                const float* src = x + ((size_t)(b0 + b) * T_ + (t + 1)) * I_ + c * 4;
                asm volatile("cp.async.cg.shared.global [%0], [%1], 16;" :: "r"(dst), "l"(src));
                asm volatile("cp.async.commit_group;" ::: "memory");
            }
            // ---- x-GEMM: warp handles K-range [wid*32, wid*32+32), all 3 gates, 4 batches ----
            ull acc[3][4];
            #pragma unroll
            for (int g = 0; g < 3; ++g)
                #pragma unroll
                for (int b = 0; b < 4; ++b) acc[g][b] = 0ull;

            const float* xq = smem + OFF_X + p * 512;
            const int kx = wid * 32;
            #pragma unroll
            for (int j = 0; j < 8; ++j) {
                const int k = kx + 4 * j;
                ulonglong2 xv0 = *reinterpret_cast<const ulonglong2*>(xq + 0 * 128 + k);
                ulonglong2 xv1 = *reinterpret_cast<const ulonglong2*>(xq + 1 * 128 + k);
                ulonglong2 xv2 = *reinterpret_cast<const ulonglong2*>(xq + 2 * 128 + k);
                ulonglong2 xv3 = *reinterpret_cast<const ulonglong2*>(xq + 3 * 128 + k);
                ulonglong2 w0 = *reinterpret_cast<const ulonglong2*>(wr0 + k);
                ulonglong2 w1 = *reinterpret_cast<const ulonglong2*>(wr1 + k);
                ulonglong2 w2 = *reinterpret_cast<const ulonglong2*>(wr2 + k);
                FFMA2(acc[0][0], w0.x, xv0.x); FFMA2(acc[0][0], w0.y, xv0.y);
                FFMA2(acc[0][1], w0.x, xv1.x); FFMA2(acc[0][1], w0.y, xv1.y);
                FFMA2(acc[0][2], w0.x, xv2.x); FFMA2(acc[0][2], w0.y, xv2.y);
                FFMA2(acc[0][3], w0.x, xv3.x); FFMA2(acc[0][3], w0.y, xv3.y);
                FFMA2(acc[1][0], w1.x, xv0.x); FFMA2(acc[1][0], w1.y, xv0.y);
                FFMA2(acc[1][1], w1.x, xv1.x); FFMA2(acc[1][1], w1.y, xv1.y);
                FFMA2(acc[1][2], w1.x, xv2.x); FFMA2(acc[1][2], w1.y, xv2.y);
                FFMA2(acc[1][3], w1.x, xv3.x); FFMA2(acc[1][3], w1.y, xv3.y);
                FFMA2(acc[2][0], w2.x, xv0.x); FFMA2(acc[2][0], w2.y, xv0.y);
                FFMA2(acc[2][1], w2.x, xv1.x); FFMA2(acc[2][1], w2.y, xv1.y);
                FFMA2(acc[2][2], w2.x, xv2.x); FFMA2(acc[2][2], w2.y, xv2.y);
                FFMA2(acc[2][3], w2.x, xv3.x); FFMA2(acc[2][3], w2.y, xv3.y);
            }
            float* px = smem + OFF_PX + p * 1536;
            #pragma unroll
            for (int g = 0; g < 3; ++g)
                #pragma unroll
                for (int b = 0; b < 4; ++b)
                    px[(((g * 4 + b) * 4) + wid) * 32 + u] = psum(acc[g][b]);

            if (t + 1 < T_)
                asm volatile("cp.async.wait_group 0;" ::: "memory");
        } else {
            // ---- poll for h_{t-1} then load it to SMEM (warp = batch) ----
            if (t > 0) {
                const unsigned target = 32u * (unsigned)t;
                while (ld_acquire(flagp) < target) { }
                const int b = wid - 4;
                const float* src = &hid[((size_t)(b0 + b) * T_ + (t - 1)) * H_];
                float4 v0 = *reinterpret_cast<const float4*>(src + u * 4);
                float4 v1 = *reinterpret_cast<const float4*>(src + 128 + u * 4);
                *reinterpret_cast<float4*>(&smem[OFF_H + p * 1024 + b * 256 + u * 4]) = v0;
                *reinterpret_cast<float4*>(&smem[OFF_H + p * 1024 + b * 256 + 128 + u * 4]) = v1;
            }
        }
        __syncthreads();   // (A) sH ready; sPx visible; x_{t+1} landed

        // ---- h-GEMM: all 8 warps, warp K-range [wid*32, wid*32+32) ----
        if (t > 0) {
            ull acc[3][4];
            #pragma unroll
            for (int g = 0; g < 3; ++g)
                #pragma unroll
                for (int b = 0; b < 4; ++b) acc[g][b] = 0ull;

            const float* hq = smem + OFF_H + p * 1024;
            const int kh = wid * 32;
            #pragma unroll
            for (int j = 0; j < 8; ++j) {
                const int k = kh + 4 * j;
                ulonglong2 hv0 = *reinterpret_cast<const ulonglong2*>(hq + 0 * 256 + k);
                ulonglong2 hv1 = *reinterpret_cast<const ulonglong2*>(hq + 1 * 256 + k);
                ulonglong2 hv2 = *reinterpret_cast<const ulonglong2*>(hq + 2 * 256 + k);
                ulonglong2 hv3 = *reinterpret_cast<const ulonglong2*>(hq + 3 * 256 + k);
                ulonglong2 w0 = *reinterpret_cast<const ulonglong2*>(wr0 + 128 + k);
                ulonglong2 w1 = *reinterpret_cast<const ulonglong2*>(wr1 + 128 + k);
                ulonglong2 w2 = *reinterpret_cast<const ulonglong2*>(wr2 + 128 + k);
                FFMA2(acc[0][0], w0.x, hv0.x); FFMA2(acc[0][0], w0.y, hv0.y);
                FFMA2(acc[0][1], w0.x, hv1.x); FFMA2(acc[0][1], w0.y, hv1.y);
                FFMA2(acc[0][2], w0.x, hv2.x); FFMA2(acc[0][2], w0.y, hv2.y);
                FFMA2(acc[0][3], w0.x, hv3.x); FFMA2(acc[0][3], w0.y, hv3.y);
                FFMA2(acc[1][0], w1.x, hv0.x); FFMA2(acc[1][0], w1.y, hv0.y);
                FFMA2(acc[1][1], w1.x, hv1.x); FFMA2(acc[1][1], w1.y, hv1.y);
                FFMA2(acc[1][2], w1.x, hv2.x); FFMA2(acc[1][2], w1.y, hv2.y);
                FFMA2(acc[1][3], w1.x, hv3.x); FFMA2(acc[1][3], w1.y, hv3.y);
                FFMA2(acc[2][0], w2.x, hv0.x); FFMA2(acc[2][0], w2.y, hv0.y);
                FFMA2(acc[2][1], w2.x, hv1.x); FFMA2(acc[2][1], w2.y, hv1.y);
                FFMA2(acc[2][2], w2.x, hv2.x); FFMA2(acc[2][2], w2.y, hv2.y);
                FFMA2(acc[2][3], w2.x, hv3.x); FFMA2(acc[2][3], w2.y, hv3.y);
            }
            float* ph = smem + OFF_PH;
            #pragma unroll
            for (int g = 0; g < 3; ++g)
                #pragma unroll
                for (int b = 0; b < 4; ++b)
                    ph[(((g * 4 + b) * 8) + wid) * 32 + u] = psum(acc[g][b]);
        }
        __syncthreads();   // (B) sPh visible

        // ---- combine: warps 0-3 (warp = batch, lane = unit) ----
        if (wid < 4) {
            const int bb = wid, uu = u;
            const float* px = smem + OFF_PX + p * 1536;
            float sx0 = 0.f, sx1 = 0.f, sx2 = 0.f;
            #pragma unroll
            for (int c = 0; c < 4; ++c) {
                sx0 += px[((0 * 4 + bb) * 4 + c) * 32 + uu];
                sx1 += px[((1 * 4 + bb) * 4 + c) * 32 + uu];
                sx2 += px[((2 * 4 + bb) * 4 + c) * 32 + uu];
            }
            float sh0 = 0.f, sh1 = 0.f, sh2 = 0.f, hprev = 0.f;
            if (t > 0) {
                const float* ph = smem + OFF_PH;
                #pragma unroll
                for (int c = 0; c < 8; ++c) {
                    sh0 += ph[((0 * 4 + bb) * 8 + c) * 32 + uu];
                    sh1 += ph[((1 * 4 + bb) * 8 + c) * 32 + uu];
                    sh2 += ph[((2 * 4 + bb) * 8 + c) * 32 + uu];
                }
                hprev = smem[OFF_H + p * 1024 + bb * 256 + u0 + uu];
            }
            const float pre_r = sx0 + sh0 + smem[OFF_BR + uu];
            const float pre_z = sx1 + sh1 + smem[OFF_BZ + uu];
            const float r = __fdividef(1.f, 1.f + __expf(-pre_r));
            const float z = __fdividef(1.f, 1.f + __expf(-pre_z));
            const float v = (sx2 + smem[OFF_BIN + uu]) + r * (sh2 + smem[OFF_BHN + uu]);
            const float nn = 1.f - __fdividef(2.f, __expf(2.f * v) + 1.f);   // tanh(v)
            const float hnew = (1.f - z) * nn + z * hprev;

            hid[((size_t)(b0 + bb) * T_ + t) * H_ + u0 + uu] = hnew;

            __syncwarp();
            if (uu == 0)
                red_release_add((unsigned*)flagp, 1u);   // per-warp publish
        }
        // no trailing barrier: flag backpressure + buffer parity make reuse safe
    }
}

// outputs[b,t] = hiddens[b,t,:] . W_o + b_o ; resets flags for graph replay
__global__ void gru_out_kernel(const float* __restrict__ Wo,
                               const float* __restrict__ bo,
                               float* __restrict__ outbuf)
{
    if (blockIdx.x == 0 && threadIdx.x < NG) g_flags[threadIdx.x] = 0u;

    int gw   = (int)((blockIdx.x * blockDim.x + threadIdx.x) >> 5);
    int lane = threadIdx.x & 31;
    if (gw >= B_ * T_) return;

    const float* hrow = outbuf + (size_t)B_ * T_ + (size_t)gw * H_;
    float s = 0.f;
    #pragma unroll
    for (int c = 0; c < 8; ++c) {
        int k = c * 32 + lane;
        s += hrow[k] * __ldg(&Wo[k]);
    }
    #pragma unroll
    for (int off = 16; off; off >>= 1)
        s += __shfl_xor_sync(0xffffffffu, s, off);
    if (lane == 0) outbuf[gw] = s + __ldg(&bo[0]);
}

extern "C" void kernel_launch(void* const* d_in, const int* in_sizes, int n_in,
                              void* d_out, int out_size)
{
    const float* x   = (const float*)d_in[0];
    const float* Wih = (const float*)d_in[1];
    const float* Whh = (const float*)d_in[2];
    const float* bih = (const float*)d_in[3];
    const float* bhh = (const float*)d_in[4];
    const float* Wo  = (const float*)d_in[5];
    const float* bo  = (const float*)d_in[6];
    float* out = (float*)d_out;

    cudaFuncSetAttribute(gru_scan_kernel,
                         cudaFuncAttributeMaxDynamicSharedMemorySize, SMEM_BYTES);

    gru_scan_kernel<<<NG * NS, THREADS, SMEM_BYTES>>>(x, Wih, Whh, bih, bhh, out);
    gru_out_kernel<<<(B_ * T_ * 32) / 256, 256>>>(Wo, bo, out);
}

// round 5
// speedup vs baseline: 2.0805x; 1.3501x over previous
#include <cuda_runtime.h>
#include <math.h>
#include <cstdint>

#define B_  64
#define T_  2048
#define I_  128
#define H_  256

#define NG 16      // batch groups
#define NS 8       // hidden slices per group
#define NB 4       // batches per group
#define NU 32      // hidden units per slice
#define THREADS 256

#define WXSTRIDE 132   // %32==4 -> conflict-free LDS.128 weight rows

// ---- SMEM layout (float offsets) ----
#define OFF_WX   0
#define SZ_WX    (3*32*WXSTRIDE)           // 12672
#define OFF_BR   (OFF_WX + SZ_WX)
#define OFF_BZ   (OFF_BR + 32)
#define OFF_BIN  (OFF_BZ + 32)
#define OFF_BHN  (OFF_BIN + 32)
#define OFF_X    (OFF_BHN + 32)            // 2 x [b][128] = 1024
#define OFF_H    (OFF_X + 1024)            // 2 x [b][256] = 2048
#define OFF_PX   (OFF_H + 2048)            // 2 x [g][b][chunk4][u] = 3072
#define OFF_PH   (OFF_PX + 3072)           // [g][b][chunk8][u] = 3072
#define SMEM_FLOATS (OFF_PH + 3072)
#define SMEM_BYTES  (SMEM_FLOATS * 4)      // ~88 KB

typedef unsigned long long ull;

__device__ unsigned g_flags[NG];           // zero-init; reset by out kernel for graph replay

__device__ __forceinline__ uint32_t smem_u32(const void* p) {
    uint32_t a;
    asm("{ .reg .u64 t; cvta.to.shared.u64 t, %1; cvt.u32.u64 %0, t; }" : "=r"(a) : "l"(p));
    return a;
}
__device__ __forceinline__ unsigned ld_acquire(const unsigned* p) {
    unsigned v;
    asm volatile("ld.global.acquire.gpu.u32 %0, [%1];" : "=r"(v) : "l"(p) : "memory");
    return v;
}
__device__ __forceinline__ void red_release_add(unsigned* p, unsigned v) {
    asm volatile("red.release.gpu.global.add.u32 [%0], %1;" :: "l"(p), "r"(v) : "memory");
}
#define FFMA2(d, a, b) \
    asm volatile("fma.rn.f32x2 %0, %1, %2, %0;" : "+l"(d) : "l"(a), "l"(b))

__device__ __forceinline__ float psum(ull v) {
    unsigned lo, hi;
    asm("mov.b64 {%0,%1}, %2;" : "=r"(lo), "=r"(hi) : "l"(v));
    return __uint_as_float(lo) + __uint_as_float(hi);
}
__device__ __forceinline__ ull packf2(float a, float b) {
    ull w;
    asm("mov.b64 %0, {%1,%2};" : "=l"(w) : "r"(__float_as_uint(a)), "r"(__float_as_uint(b)));
    return w;
}

__global__ void __launch_bounds__(THREADS, 1)
gru_scan_kernel(const float* __restrict__ x,
                const float* __restrict__ Wih,
                const float* __restrict__ Whh,
                const float* __restrict__ bih,
                const float* __restrict__ bhh,
                float* __restrict__ outbuf)
{
    extern __shared__ float smem[];
    const int tid = threadIdx.x;
    const int cta = blockIdx.x;
    const int grp = cta >> 3;
    const int slc = cta & 7;
    const int b0  = grp * NB;
    const int u0  = slc * NU;
    const uint32_t sbase = smem_u32(smem);

    float* hid = outbuf + (size_t)B_ * T_;   // hiddens [B][T][H]

    const int wid = tid >> 5;
    const int u   = tid & 31;
    const int kw  = wid * 32;                // this warp's K-chunk of W_hh
    const unsigned* flagp = &g_flags[grp];

    // ---- one-time: W_ih slice into SMEM [g][u][k] (stride WXSTRIDE) ----
    for (int rk = tid; rk < 96 * 128; rk += THREADS) {
        int row = rk >> 7;
        int k   = rk & 127;
        int g   = row >> 5;
        int uu  = row & 31;
        smem[OFF_WX + (g * 32 + uu) * WXSTRIDE + k] =
            Wih[(size_t)(g * 256 + u0 + uu) * I_ + k];
    }
    if (tid < 32) {
        int uu = tid;
        smem[OFF_BR  + uu] = bih[0 * 256 + u0 + uu] + bhh[0 * 256 + u0 + uu];
        smem[OFF_BZ  + uu] = bih[1 * 256 + u0 + uu] + bhh[1 * 256 + u0 + uu];
        smem[OFF_BIN + uu] = bih[2 * 256 + u0 + uu];
        smem[OFF_BHN + uu] = bhh[2 * 256 + u0 + uu];
    }
    // preload x_0 into buffer 0: layout [b][k]
    for (int e = tid; e < 512; e += THREADS) {
        int b = e >> 7, k = e & 127;
        smem[OFF_X + e] = x[((size_t)(b0 + b) * T_ + 0) * I_ + k];
    }

    // ---- one-time: W_hh into REGISTERS: wh[g*16+j] = {W[g,u][kw+2j], W[g,u][kw+2j+1]} ----
    ull wh[48];
    #pragma unroll
    for (int g = 0; g < 3; ++g) {
        const float* row = Whh + (size_t)(g * 256 + u0 + u) * H_ + kw;
        #pragma unroll
        for (int j = 0; j < 16; ++j) {
            float2 v = *reinterpret_cast<const float2*>(row + 2 * j);
            wh[g * 16 + j] = packf2(v.x, v.y);
        }
    }
    __syncthreads();

    // per-lane x-weight row bases (gates)
    const float* wx0 = smem + OFF_WX + (0 * 32 + u) * WXSTRIDE;
    const float* wx1 = smem + OFF_WX + (1 * 32 + u) * WXSTRIDE;
    const float* wx2 = smem + OFF_WX + (2 * 32 + u) * WXSTRIDE;

    for (int t = 0; t < T_; ++t) {
        const int p = t & 1;
        const int q = p ^ 1;

        if (wid < 4) {
            // ---- prefetch x_{t+1} ----
            if (t + 1 < T_) {
                int b = wid, c = u;
                uint32_t dst = sbase + (OFF_X + q * 512 + b * 128 + c * 4) * 4;
                const float* src = x + ((size_t)(b0 + b) * T_ + (t + 1)) * I_ + c * 4;
                asm volatile("cp.async.cg.shared.global [%0], [%1], 16;" :: "r"(dst), "l"(src));
                asm volatile("cp.async.commit_group;" ::: "memory");
            }
            // ---- x-GEMM: warp covers k in [wid*32, wid*32+32) ----
            ull acc[12];
            #pragma unroll
            for (int i = 0; i < 12; ++i) acc[i] = 0ull;

            const float* xq = smem + OFF_X + p * 512;
            const int kx = wid * 32;
            #pragma unroll
            for (int j = 0; j < 8; ++j) {
                const int k = kx + 4 * j;
                ulonglong2 xv0 = *reinterpret_cast<const ulonglong2*>(xq + 0 * 128 + k);
                ulonglong2 xv1 = *reinterpret_cast<const ulonglong2*>(xq + 1 * 128 + k);
                ulonglong2 xv2 = *reinterpret_cast<const ulonglong2*>(xq + 2 * 128 + k);
                ulonglong2 xv3 = *reinterpret_cast<const ulonglong2*>(xq + 3 * 128 + k);
                ulonglong2 w0 = *reinterpret_cast<const ulonglong2*>(wx0 + k);
                ulonglong2 w1 = *reinterpret_cast<const ulonglong2*>(wx1 + k);
                ulonglong2 w2 = *reinterpret_cast<const ulonglong2*>(wx2 + k);
                FFMA2(acc[0], w0.x, xv0.x); FFMA2(acc[0], w0.y, xv0.y);
                FFMA2(acc[1], w0.x, xv1.x); FFMA2(acc[1], w0.y, xv1.y);
                FFMA2(acc[2], w0.x, xv2.x); FFMA2(acc[2], w0.y, xv2.y);
                FFMA2(acc[3], w0.x, xv3.x); FFMA2(acc[3], w0.y, xv3.y);
                FFMA2(acc[4], w1.x, xv0.x); FFMA2(acc[4], w1.y, xv0.y);
                FFMA2(acc[5], w1.x, xv1.x); FFMA2(acc[5], w1.y, xv1.y);
                FFMA2(acc[6], w1.x, xv2.x); FFMA2(acc[6], w1.y, xv2.y);
                FFMA2(acc[7], w1.x, xv3.x); FFMA2(acc[7], w1.y, xv3.y);
                FFMA2(acc[8], w2.x, xv0.x); FFMA2(acc[8], w2.y, xv0.y);
                FFMA2(acc[9], w2.x, xv1.x); FFMA2(acc[9], w2.y, xv1.y);
                FFMA2(acc[10], w2.x, xv2.x); FFMA2(acc[10], w2.y, xv2.y);
                FFMA2(acc[11], w2.x, xv3.x); FFMA2(acc[11], w2.y, xv3.y);
            }
            float* px = smem + OFF_PX + p * 1536;
            #pragma unroll
            for (int g = 0; g < 3; ++g)
                #pragma unroll
                for (int b = 0; b < 4; ++b)
                    px[((g * 4 + b) * 4 + wid) * 32 + u] = psum(acc[g * 4 + b]);

            if (t + 1 < T_)
                asm volatile("cp.async.wait_group 0;" ::: "memory");
        } else {
            // ---- poll (warp 4 only), then loaders bring h_{t-1} into SMEM ----
            if (t > 0) {
                if (wid == 4) {
                    const unsigned target = 8u * (unsigned)t;
                    while (ld_acquire(flagp) < target) { }
                }
                asm volatile("bar.sync 1, 128;" ::: "memory");   // warps 4-7
                const int b = wid - 4;
                const float* src = &hid[((size_t)(b0 + b) * T_ + (t - 1)) * H_];
                float4 v0 = *reinterpret_cast<const float4*>(src + u * 4);
                float4 v1 = *reinterpret_cast<const float4*>(src + 128 + u * 4);
                *reinterpret_cast<float4*>(&smem[OFF_H + p * 1024 + b * 256 + u * 4]) = v0;
                *reinterpret_cast<float4*>(&smem[OFF_H + p * 1024 + b * 256 + 128 + u * 4]) = v1;
            }
        }
        __syncthreads();   // (A) sH ready; x_{t+1} landed

        // ---- h-GEMM: all 8 warps, weights from registers ----
        if (t > 0) {
            ull acc[12];
            #pragma unroll
            for (int i = 0; i < 12; ++i) acc[i] = 0ull;

            const float* hq = smem + OFF_H + p * 1024;
            #pragma unroll
            for (int jj = 0; jj < 8; ++jj) {
                const int k = kw + 4 * jj;
                ulonglong2 h0 = *reinterpret_cast<const ulonglong2*>(hq + 0 * 256 + k);
                ulonglong2 h1 = *reinterpret_cast<const ulonglong2*>(hq + 1 * 256 + k);
                ulonglong2 h2 = *reinterpret_cast<const ulonglong2*>(hq + 2 * 256 + k);
                ulonglong2 h3 = *reinterpret_cast<const ulonglong2*>(hq + 3 * 256 + k);
                #pragma unroll
                for (int g = 0; g < 3; ++g) {
                    const ull wa = wh[g * 16 + 2 * jj];
                    const ull wb = wh[g * 16 + 2 * jj + 1];
                    FFMA2(acc[g * 4 + 0], wa, h0.x); FFMA2(acc[g * 4 + 0], wb, h0.y);
                    FFMA2(acc[g * 4 + 1], wa, h1.x); FFMA2(acc[g * 4 + 1], wb, h1.y);
                    FFMA2(acc[g * 4 + 2], wa, h2.x); FFMA2(acc[g * 4 + 2], wb, h2.y);
                    FFMA2(acc[g * 4 + 3], wa, h3.x); FFMA2(acc[g * 4 + 3], wb, h3.y);
                }
            }
            float* ph = smem + OFF_PH;
            #pragma unroll
            for (int g = 0; g < 3; ++g)
                #pragma unroll
                for (int b = 0; b < 4; ++b)
                    ph[((g * 4 + b) * 8 + wid) * 32 + u] = psum(acc[g * 4 + b]);
        }
        __syncthreads();   // (B) sPh visible

        // ---- combine + publish: warps 0-3 (warp = batch, lane = unit) ----
        if (wid < 4) {
            const int bb = wid, uu = u;
            const float* px = smem + OFF_PX + p * 1536;
            float sx0 = 0.f, sx1 = 0.f, sx2 = 0.f;
            #pragma unroll
            for (int c = 0; c < 4; ++c) {
                sx0 += px[((0 * 4 + bb) * 4 + c) * 32 + uu];
                sx1 += px[((1 * 4 + bb) * 4 + c) * 32 + uu];
                sx2 += px[((2 * 4 + bb) * 4 + c) * 32 + uu];
            }
            float sh0 = 0.f, sh1 = 0.f, sh2 = 0.f, hprev = 0.f;
            if (t > 0) {
                const float* ph = smem + OFF_PH;
                #pragma unroll
                for (int c = 0; c < 8; ++c) {
                    sh0 += ph[((0 * 4 + bb) * 8 + c) * 32 + uu];
                    sh1 += ph[((1 * 4 + bb) * 8 + c) * 32 + uu];
                    sh2 += ph[((2 * 4 + bb) * 8 + c) * 32 + uu];
                }
                hprev = smem[OFF_H + p * 1024 + bb * 256 + u0 + uu];
            }
            const float pre_r = sx0 + sh0 + smem[OFF_BR + uu];
            const float pre_z = sx1 + sh1 + smem[OFF_BZ + uu];
            const float r = __fdividef(1.f, 1.f + __expf(-pre_r));
            const float z = __fdividef(1.f, 1.f + __expf(-pre_z));
            const float v = (sx2 + smem[OFF_BIN + uu]) + r * (sh2 + smem[OFF_BHN + uu]);
            const float nn = 1.f - __fdividef(2.f, __expf(2.f * v) + 1.f);   // tanh(v)
            const float hnew = (1.f - z) * nn + z * hprev;

            hid[((size_t)(b0 + bb) * T_ + t) * H_ + u0 + uu] = hnew;

            asm volatile("bar.sync 2, 128;" ::: "memory");   // warps 0-3: h stores done
            if (tid == 0)
                red_release_add((unsigned*)flagp, 1u);        // single publish per CTA
        }
        // no trailing syncthreads: buffer parity + flag backpressure make reuse safe
    }
}

// outputs[b,t] = hiddens[b,t,:] . W_o + b_o ; resets flags for graph replay
__global__ void gru_out_kernel(const float* __restrict__ Wo,
                               const float* __restrict__ bo,
                               float* __restrict__ outbuf)
{
    if (blockIdx.x == 0 && threadIdx.x < NG) g_flags[threadIdx.x] = 0u;

    int gw   = (int)((blockIdx.x * blockDim.x + threadIdx.x) >> 5);
    int lane = threadIdx.x & 31;
    if (gw >= B_ * T_) return;

    const float* hrow = outbuf + (size_t)B_ * T_ + (size_t)gw * H_;
    float s = 0.f;
    #pragma unroll
    for (int c = 0; c < 8; ++c) {
        int k = c * 32 + lane;
        s += hrow[k] * __ldg(&Wo[k]);
    }
    #pragma unroll
    for (int off = 16; off; off >>= 1)
        s += __shfl_xor_sync(0xffffffffu, s, off);
    if (lane == 0) outbuf[gw] = s + __ldg(&bo[0]);
}

extern "C" void kernel_launch(void* const* d_in, const int* in_sizes, int n_in,
                              void* d_out, int out_size)
{
    const float* x   = (const float*)d_in[0];
    const float* Wih = (const float*)d_in[1];
    const float* Whh = (const float*)d_in[2];
    const float* bih = (const float*)d_in[3];
    const float* bhh = (const float*)d_in[4];
    const float* Wo  = (const float*)d_in[5];
    const float* bo  = (const float*)d_in[6];
    float* out = (float*)d_out;

    cudaFuncSetAttribute(gru_scan_kernel,
                         cudaFuncAttributeMaxDynamicSharedMemorySize, SMEM_BYTES);

    gru_scan_kernel<<<NG * NS, THREADS, SMEM_BYTES>>>(x, Wih, Whh, bih, bhh, out);
    gru_out_kernel<<<(B_ * T_ * 32) / 256, 256>>>(Wo, bo, out);
}